// round 16
// baseline (speedup 1.0000x reference)
#include <cuda_runtime.h>
#include <cuda_bf16.h>
#include <cstdint>

// Problem constants
#define NN 2048
#define BB 256
#define TT 256
#define CC 2
#define SLOPE 8.0f

// GEMM tiling: CTA 64x64, k-chunk 128, 512 threads (16 warps = 8 wg x 2m)
// Warp tile 32x64: 12 ldsm.x4 -> 48 MMA per chunk (4:1 vs prior 3:1).
#define BM 64
#define BN 64
#define BK 128
#define NIT (NN / BK)   // 16
#define THREADS 512

#define TILE_B (64 * 256)         // 16384 B: 64 rows x 128 bf16 (256B/row)
#define STAGE_B (4 * TILE_B)      // Ah, Al, Bh, Bl = 65536 B
#define NSTAGE 3
#define SMEM_PAR 0                // 7 x 64 floats = 1792 B
#define SMEM_STAGE 2048
#define SMEM_TOTAL (SMEM_STAGE + NSTAGE * STAGE_B)  // 198656 B

// Scratch, double-buffered in t-parity (allocation-free rule)
__device__ __align__(256) __nv_bfloat16 g_a_hi[2 * BB * NN];
__device__ __align__(256) __nv_bfloat16 g_a_lo[2 * BB * NN];
__device__ __align__(256) __nv_bfloat16 g_w_hi[NN * NN];
__device__ __align__(256) __nv_bfloat16 g_w_lo[NN * NN];

// ---------------------------------------------------------------------------
__device__ __forceinline__ uint32_t s2u(const void* p) {
    uint32_t a;
    asm("{ .reg .u64 t; cvta.to.shared.u64 t, %1; cvt.u32.u64 %0, t; }"
        : "=r"(a) : "l"(p));
    return a;
}

__device__ __forceinline__ void cp16(uint32_t dst, const void* src) {
    asm volatile("cp.async.cg.shared.global [%0], [%1], 16;\n"
                 :: "r"(dst), "l"(src));
}
#define CP_COMMIT() asm volatile("cp.async.commit_group;\n" ::: "memory")
#define CP_WAIT(n)  asm volatile("cp.async.wait_group %0;\n" :: "n"(n) : "memory")

__device__ __forceinline__ void ldsm4(uint32_t* r, uint32_t addr) {
    asm volatile("ldmatrix.sync.aligned.m8n8.x4.shared.b16 {%0,%1,%2,%3}, [%4];"
                 : "=r"(r[0]), "=r"(r[1]), "=r"(r[2]), "=r"(r[3]) : "r"(addr));
}

__device__ __forceinline__ void mma16816(float* c, const uint32_t* a,
                                         uint32_t b0, uint32_t b1) {
    asm volatile("mma.sync.aligned.m16n8k16.row.col.f32.bf16.bf16.f32 "
                 "{%0,%1,%2,%3}, {%4,%5,%6,%7}, {%8,%9}, {%0,%1,%2,%3};"
                 : "+f"(c[0]), "+f"(c[1]), "+f"(c[2]), "+f"(c[3])
                 : "r"(a[0]), "r"(a[1]), "r"(a[2]), "r"(a[3]),
                   "r"(b0), "r"(b1));
}

// ---------------------------------------------------------------------------
__global__ void zero_kernel(float* __restrict__ out, int n) {
    int i = blockIdx.x * blockDim.x + threadIdx.x;
    if (i < n) out[i] = 0.0f;
}

// W fp32 -> hi/lo bf16 (once per launch)
__global__ void wconv_kernel(const float* __restrict__ W) {
    int i = blockIdx.x * blockDim.x + threadIdx.x;
    if (i < NN * NN) {
        float w = W[i];
        __nv_bfloat16 h = __float2bfloat16_rn(w);
        g_w_hi[i] = h;
        g_w_lo[i] = __float2bfloat16_rn(w - __bfloat162float(h));
    }
}

// s'(0) = state0 + mask * ext(t=0), split hi/lo, into parity-0 buffer
__global__ void prep0_kernel(const float* __restrict__ state0,
                             const float* __restrict__ inputs,
                             const float* __restrict__ mask,
                             const float* __restrict__ enc) {
    int i = blockIdx.x * blockDim.x + threadIdx.x;
    int b = i >> 11;
    int n = i & (NN - 1);
    float x0 = inputs[b * TT];
    float x1 = inputs[(BB + b) * TT];
    float sp = state0[i] + mask[n] * (x0 * enc[n] + x1 * enc[NN + n]);
    __nv_bfloat16 h = __float2bfloat16_rn(sp);
    g_a_hi[i] = h;
    g_a_lo[i] = __float2bfloat16_rn(sp - __bfloat162float(h));
}

// ---------------------------------------------------------------------------
// Fused step kernel: pre = s'@W^T via 3x bf16 HMMA (hi*hi + hi*lo + lo*hi).
// 16 warps = 8 k-split warpgroups x 2 m-warps; warp tile 32x64; BK=128
// chunks (each wg owns one k16 slice); 8-way smem reduction; distributed
// sigmoid/decoder/state epilogue.
__global__ void __launch_bounds__(THREADS, 1)
step_kernel(const float* __restrict__ inputs,
            const float* __restrict__ mask,
            const float* __restrict__ bias,
            const float* __restrict__ thr,
            const float* __restrict__ dec,
            const float* __restrict__ enc,
            float* __restrict__ out,
            int t) {
    extern __shared__ char smem[];
    const uint32_t sbase = s2u(smem);
    const int tid = threadIdx.x;
    const int wid = tid >> 5;
    const int lid = tid & 31;
    const int wg = wid >> 1;    // 0..7 : k16 slice within BK=128 chunk
    const int wm = wid & 1;     // 0..1 : 32-row m tile
    const int n0 = blockIdx.x * BN;
    const int m0 = blockIdx.y * BM;

    const __nv_bfloat16* a_hi_r = g_a_hi + (size_t)(t & 1) * (BB * NN);
    const __nv_bfloat16* a_lo_r = g_a_lo + (size_t)(t & 1) * (BB * NN);
    __nv_bfloat16* a_hi_w = g_a_hi + (size_t)((t + 1) & 1) * (BB * NN);
    __nv_bfloat16* a_lo_w = g_a_lo + (size_t)((t + 1) & 1) * (BB * NN);

    // epilogue params into smem: [mask|bias|thr|dec0|dec1|enc0|enc1] x 64
    if (tid < 64) {
        float* pp = (float*)(smem + SMEM_PAR);
        int n = n0 + tid;
        pp[tid]       = mask[n];
        pp[64 + tid]  = bias[n];
        pp[128 + tid] = thr[n];
        pp[192 + tid] = dec[n];
        pp[256 + tid] = dec[NN + n];
        pp[320 + tid] = enc[n];
        pp[384 + tid] = enc[NN + n];
    }

    // ---- Fill: 512 threads, 8 cp16 each (4 tiles x rows frow, frow+32) ----
    const int frow = tid >> 4;       // 0..31
    const int fch = tid & 15;        // 16B chunk within 256B row
    const uint32_t fdst = frow * 256 + ((fch ^ (frow & 7)) << 4);
    const __nv_bfloat16* pAh = a_hi_r + (size_t)(m0 + frow) * NN + fch * 8;
    const __nv_bfloat16* pAl = a_lo_r + (size_t)(m0 + frow) * NN + fch * 8;
    const __nv_bfloat16* pWh = g_w_hi + (size_t)(n0 + frow) * NN + fch * 8;
    const __nv_bfloat16* pWl = g_w_lo + (size_t)(n0 + frow) * NN + fch * 8;
    const size_t rstep = (size_t)32 * NN;   // +32 rows
    uint32_t fstage = 0;

    auto fill = [&]() {
        const uint32_t sb = sbase + SMEM_STAGE + fstage * STAGE_B;
        cp16(sb + 0 * TILE_B + fdst, pAh);
        cp16(sb + 0 * TILE_B + fdst + 8192, pAh + rstep);
        cp16(sb + 1 * TILE_B + fdst, pAl);
        cp16(sb + 1 * TILE_B + fdst + 8192, pAl + rstep);
        cp16(sb + 2 * TILE_B + fdst, pWh);
        cp16(sb + 2 * TILE_B + fdst + 8192, pWh + rstep);
        cp16(sb + 3 * TILE_B + fdst, pWl);
        cp16(sb + 3 * TILE_B + fdst + 8192, pWl + rstep);
        CP_COMMIT();
        pAh += BK; pAl += BK; pWh += BK; pWl += BK;
        fstage = (fstage == NSTAGE - 1) ? 0 : fstage + 1;
    };

    fill();
    fill();

    // ---- ldsm offsets (constants per thread; kch = this wg's k16 slice) ----
    const int lrow8 = lid & 7;
    const int lgrp = lid >> 3;
    const int kch = (wg << 1) | (lgrp >> 1);
    uint32_t aoff[2], boff[4];
#pragma unroll
    for (int mi = 0; mi < 2; mi++) {
        int row = wm * 32 + mi * 16 + (lgrp & 1) * 8 + lrow8;
        aoff[mi] = row * 256 + ((kch ^ (row & 7)) << 4);
    }
#pragma unroll
    for (int ni = 0; ni < 4; ni++) {
        int row = ni * 16 + (lgrp & 1) * 8 + lrow8;
        boff[ni] = row * 256 + ((kch ^ (row & 7)) << 4);
    }

    float acc[2][8][4];   // [mi][q = ni*2+nh][4]
#pragma unroll
    for (int i = 0; i < 2; i++)
#pragma unroll
        for (int q = 0; q < 8; q++)
#pragma unroll
            for (int r = 0; r < 4; r++) acc[i][q][r] = 0.0f;

    uint32_t cstage = 0;
#pragma unroll 1
    for (int c = 0; c < NIT; c++) {
        const uint32_t sb = sbase + SMEM_STAGE + cstage * STAGE_B;
        cstage = (cstage == NSTAGE - 1) ? 0 : cstage + 1;

        if (c == NIT - 1) { CP_WAIT(0); } else { CP_WAIT(1); }
        __syncthreads();     // publish fills; protect stage (c-1)%3 reuse

        // hh fragments
        uint32_t ah[2][4], bh[4][4];
#pragma unroll
        for (int mi = 0; mi < 2; mi++) ldsm4(ah[mi], sb + 0 * TILE_B + aoff[mi]);
#pragma unroll
        for (int ni = 0; ni < 4; ni++) ldsm4(bh[ni], sb + 2 * TILE_B + boff[ni]);

        // pass 1: hh
#pragma unroll
        for (int mi = 0; mi < 2; mi++)
#pragma unroll
            for (int q = 0; q < 8; q++)
                mma16816(acc[mi][q], ah[mi], bh[q >> 1][q & 1],
                         bh[q >> 1][(q & 1) + 2]);

        if (c + 2 < NIT) fill();

        // lo fragments (loads hidden behind pass 1)
        uint32_t al[2][4], bl[4][4];
#pragma unroll
        for (int mi = 0; mi < 2; mi++) ldsm4(al[mi], sb + 1 * TILE_B + aoff[mi]);
#pragma unroll
        for (int ni = 0; ni < 4; ni++) ldsm4(bl[ni], sb + 3 * TILE_B + boff[ni]);

        // pass 2: hi * lo
#pragma unroll
        for (int mi = 0; mi < 2; mi++)
#pragma unroll
            for (int q = 0; q < 8; q++)
                mma16816(acc[mi][q], ah[mi], bl[q >> 1][q & 1],
                         bl[q >> 1][(q & 1) + 2]);
        // pass 3: lo * hi
#pragma unroll
        for (int mi = 0; mi < 2; mi++)
#pragma unroll
            for (int q = 0; q < 8; q++)
                mma16816(acc[mi][q], al[mi], bh[q >> 1][q & 1],
                         bh[q >> 1][(q & 1) + 2]);
    }

    // ---- Dump all accumulators to smem in (wg, m, n) layout ----
    __syncthreads();
    float* red = (float*)(smem + SMEM_STAGE);   // 8 x 16KB, reuses stage area
    {
        const int mb = wm * 32 + (lid >> 2);
        const int nb = (lid & 3) << 1;
        float* rg = red + (wg << 12);           // wg * 4096 floats
#pragma unroll
        for (int mi = 0; mi < 2; mi++)
#pragma unroll
            for (int q = 0; q < 8; q++)
#pragma unroll
                for (int rr = 0; rr < 4; rr++) {
                    int m = mb + mi * 16 + ((rr >> 1) << 3);
                    int n = nb + q * 8 + (rr & 1);
                    rg[m * 64 + n] = acc[mi][q][rr];
                }
    }
    __syncthreads();

    // ---- Distributed epilogue: thread -> (row em, 8 cols at en) ----
    const float* pp = (const float*)(smem + SMEM_PAR);
    const bool hasn = (t + 1 < TT);
    const int em = tid >> 3;          // 0..63
    const int en = (tid & 7) << 3;    // 0,8,...,56
    const int b = m0 + em;

    float pre[8];
    {
        const float* r0 = red + em * 64 + en;
        float4 u0 = *(const float4*)(r0);
        float4 u1 = *(const float4*)(r0 + 4);
#pragma unroll
        for (int g = 1; g < 8; g++) {
            const float* rg = r0 + (g << 12);
            float4 v0 = *(const float4*)(rg);
            float4 v1 = *(const float4*)(rg + 4);
            u0.x += v0.x; u0.y += v0.y; u0.z += v0.z; u0.w += v0.w;
            u1.x += v1.x; u1.y += v1.y; u1.z += v1.z; u1.w += v1.w;
        }
        pre[0] = u0.x; pre[1] = u0.y; pre[2] = u0.z; pre[3] = u0.w;
        pre[4] = u1.x; pre[5] = u1.y; pre[6] = u1.z; pre[7] = u1.w;
    }

    float x0 = 0.0f, x1 = 0.0f;
    if (hasn) {
        x0 = inputs[b * TT + t + 1];
        x1 = inputs[(BB + b) * TT + t + 1];
    }
    float p0 = 0.0f, p1 = 0.0f;
    __nv_bfloat16 hb[8], lb[8];
#pragma unroll
    for (int j = 0; j < 8; j++) {
        int nl = en + j;
        float mk = pp[nl];
        float z = SLOPE * (pre[j] - pp[128 + nl]);
        float sg = 1.0f / (1.0f + __expf(-z));
        float ns = mk * (pp[64 + nl] + sg);
        p0 = fmaf(ns, pp[192 + nl], p0);
        p1 = fmaf(ns, pp[256 + nl], p1);
        float sp = fmaf(mk, fmaf(x0, pp[320 + nl], x1 * pp[384 + nl]), ns);
        __nv_bfloat16 h = __float2bfloat16_rn(sp);
        hb[j] = h;
        lb[j] = __float2bfloat16_rn(sp - __bfloat162float(h));
    }
    if (hasn) {
        *(uint4*)(a_hi_w + (size_t)b * NN + n0 + en) = *(uint4*)hb;
        *(uint4*)(a_lo_w + (size_t)b * NN + n0 + en) = *(uint4*)lb;
    }

    // reduce decoder partials over the 8 lanes covering this row
    p0 += __shfl_xor_sync(0xffffffffu, p0, 1);
    p0 += __shfl_xor_sync(0xffffffffu, p0, 2);
    p0 += __shfl_xor_sync(0xffffffffu, p0, 4);
    p1 += __shfl_xor_sync(0xffffffffu, p1, 1);
    p1 += __shfl_xor_sync(0xffffffffu, p1, 2);
    p1 += __shfl_xor_sync(0xffffffffu, p1, 4);
    if ((lid & 7) == 0) {
        atomicAdd(&out[b * TT + t], p0);               // c = 0
        atomicAdd(&out[(BB + b) * TT + t], p1);        // c = 1
    }
}

// ---------------------------------------------------------------------------
extern "C" void kernel_launch(void* const* d_in, const int* in_sizes, int n_in,
                              void* d_out, int out_size) {
    const float* inputs = (const float*)d_in[0];  // [C,B,T]
    const float* state0 = (const float*)d_in[1];  // [B,N]
    const float* mask   = (const float*)d_in[2];  // [N]
    const float* enc    = (const float*)d_in[3];  // [C,N]
    const float* dec    = (const float*)d_in[4];  // [C,N]
    const float* W      = (const float*)d_in[5];  // [N,N]
    const float* bias   = (const float*)d_in[6];  // [N]
    const float* thr    = (const float*)d_in[7];  // [N]
    float* out = (float*)d_out;                   // [C,B,T]

    cudaFuncSetAttribute(step_kernel,
                         cudaFuncAttributeMaxDynamicSharedMemorySize, SMEM_TOTAL);

    zero_kernel<<<(CC * BB * TT + 255) / 256, 256>>>(out, CC * BB * TT);
    wconv_kernel<<<(NN * NN + 255) / 256, 256>>>(W);
    prep0_kernel<<<(BB * NN + 255) / 256, 256>>>(state0, inputs, mask, enc);

    dim3 grid(NN / BN, BB / BM);  // (32, 4) = 128 CTAs
    for (int t = 0; t < TT; t++) {
        step_kernel<<<grid, THREADS, SMEM_TOTAL>>>(inputs, mask, bias, thr,
                                                   dec, enc, out, t);
    }
}